// round 1
// baseline (speedup 1.0000x reference)
#include <cuda_runtime.h>

#define B 128
#define K 17
#define HW 9216          // 96*96
#define NVEC (HW/4)      // 2304
#define TOPK 8
#define THREADS1 256

__device__ float g_per_joint[B * K];

__global__ void __launch_bounds__(THREADS1, 4)
mse_per_joint_kernel(const float* __restrict__ pred,
                     const float* __restrict__ gt,
                     const float* __restrict__ tw) {
    const int bk = blockIdx.x;                    // 0 .. B*K-1
    const float4* __restrict__ p = reinterpret_cast<const float4*>(pred + (size_t)bk * HW);
    const float4* __restrict__ g = reinterpret_cast<const float4*>(gt   + (size_t)bk * HW);
    const float w = tw[bk];

    float acc = 0.0f;
    #pragma unroll
    for (int i = threadIdx.x; i < NVEC; i += THREADS1) {
        float4 a = p[i];
        float4 b = g[i];
        float d0 = (a.x - b.x) * w;
        float d1 = (a.y - b.y) * w;
        float d2 = (a.z - b.z) * w;
        float d3 = (a.w - b.w) * w;
        acc += d0 * d0 + d1 * d1 + d2 * d2 + d3 * d3;
    }

    // warp reduce
    #pragma unroll
    for (int off = 16; off > 0; off >>= 1)
        acc += __shfl_down_sync(0xFFFFFFFFu, acc, off);

    __shared__ float warp_sums[THREADS1 / 32];
    const int lane = threadIdx.x & 31;
    const int wid  = threadIdx.x >> 5;
    if (lane == 0) warp_sums[wid] = acc;
    __syncthreads();

    if (wid == 0) {
        float v = (lane < THREADS1 / 32) ? warp_sums[lane] : 0.0f;
        #pragma unroll
        for (int off = 4; off > 0; off >>= 1)
            v += __shfl_down_sync(0xFFFFFFFFu, v, off);
        if (lane == 0) g_per_joint[bk] = v * (1.0f / (float)HW);
    }
}

__global__ void __launch_bounds__(B, 1)
ohkm_topk_kernel(float* __restrict__ out) {
    const int b = threadIdx.x;   // one thread per sample
    float v[K];
    #pragma unroll
    for (int i = 0; i < K; i++)
        v[i] = g_per_joint[b * K + i];

    // 8-pass selection of max values
    float s = 0.0f;
    #pragma unroll
    for (int t = 0; t < TOPK; t++) {
        float m = v[0];
        int mi = 0;
        #pragma unroll
        for (int i = 1; i < K; i++) {
            if (v[i] > m) { m = v[i]; mi = i; }
        }
        s += m;
        v[mi] = -3.4e38f;
    }

    __shared__ float sh[B];
    sh[b] = s;
    __syncthreads();
    #pragma unroll
    for (int stride = B / 2; stride > 0; stride >>= 1) {
        if (b < stride) sh[b] += sh[b + stride];
        __syncthreads();
    }
    if (b == 0)
        out[0] = sh[0] * (1.0f / (float)(B * TOPK));
}

extern "C" void kernel_launch(void* const* d_in, const int* in_sizes, int n_in,
                              void* d_out, int out_size) {
    const float* pred = (const float*)d_in[0];   // output [B,K,H,W]
    const float* gt   = (const float*)d_in[1];   // target [B,K,H,W]
    const float* tw   = (const float*)d_in[2];   // target_weight [B,K,1]
    float* out = (float*)d_out;

    mse_per_joint_kernel<<<B * K, THREADS1>>>(pred, gt, tw);
    ohkm_topk_kernel<<<1, B>>>(out);
}